// round 8
// baseline (speedup 1.0000x reference)
#include <cuda_runtime.h>
#include <math.h>

namespace {
constexpr int B_ = 4;
constexpr int T_ = 4096;
constexpr int D_ = 1024;
constexpr int A_ = 1024;
}

// Static scratch (allocation-free kernel_launch): Q, K, V (64 MB each) and scores (256 MB).
__device__ __align__(16) float g_q[B_ * T_ * A_];
__device__ __align__(16) float g_k[B_ * T_ * A_];
__device__ __align__(16) float g_v[B_ * T_ * A_];
__device__ __align__(16) float g_s[B_ * T_ * T_];

// ---------------------------------------------------------------------------
// Kernel 1: QKV projection. C[m,a] = sum_d X[m,d] * W[a,d]  (both K-contiguous)
// blockIdx.z selects {Wq->g_q, Wk->g_k, Wv->g_v}. Tiles: 128x128x16.
// ---------------------------------------------------------------------------
__global__ __launch_bounds__(256) void qkv_kernel(const float* __restrict__ X,
                                                  const float* __restrict__ Wq,
                                                  const float* __restrict__ Wk,
                                                  const float* __restrict__ Wv) {
    __shared__ float As[16][128];
    __shared__ float Bs[16][128];
    const int z = blockIdx.z;
    const float* W = (z == 0) ? Wq : (z == 1) ? Wk : Wv;
    float* C = (z == 0) ? g_q : (z == 1) ? g_k : g_v;
    const int m0 = blockIdx.y * 128;
    const int n0 = blockIdx.x * 128;
    const int tid = threadIdx.x;
    const int tr = tid >> 4, tc = tid & 15;

    float acc[8][8] = {};
    for (int k0 = 0; k0 < D_; k0 += 16) {
#pragma unroll
        for (int l = 0; l < 2; l++) {
            int f = tid + l * 256;
            int row = f >> 2, c4 = (f & 3) << 2;
            float4 va = *reinterpret_cast<const float4*>(X + (size_t)(m0 + row) * D_ + k0 + c4);
            As[c4 + 0][row] = va.x; As[c4 + 1][row] = va.y;
            As[c4 + 2][row] = va.z; As[c4 + 3][row] = va.w;
            float4 vb = *reinterpret_cast<const float4*>(W + (size_t)(n0 + row) * D_ + k0 + c4);
            Bs[c4 + 0][row] = vb.x; Bs[c4 + 1][row] = vb.y;
            Bs[c4 + 2][row] = vb.z; Bs[c4 + 3][row] = vb.w;
        }
        __syncthreads();
#pragma unroll
        for (int kk = 0; kk < 16; kk++) {
            float a[8], b[8];
            *(float4*)(a)     = *(const float4*)(&As[kk][tr * 8]);
            *(float4*)(a + 4) = *(const float4*)(&As[kk][tr * 8 + 4]);
            *(float4*)(b)     = *(const float4*)(&Bs[kk][tc * 8]);
            *(float4*)(b + 4) = *(const float4*)(&Bs[kk][tc * 8 + 4]);
#pragma unroll
            for (int i = 0; i < 8; i++)
#pragma unroll
                for (int j = 0; j < 8; j++)
                    acc[i][j] += a[i] * b[j];
        }
        __syncthreads();
    }
#pragma unroll
    for (int i = 0; i < 8; i++) {
        float4* cp = reinterpret_cast<float4*>(C + (size_t)(m0 + tr * 8 + i) * A_ + n0 + tc * 8);
        cp[0] = make_float4(acc[i][0], acc[i][1], acc[i][2], acc[i][3]);
        cp[1] = make_float4(acc[i][4], acc[i][5], acc[i][6], acc[i][7]);
    }
}

// ---------------------------------------------------------------------------
// Kernel 2: causal scores. S[b,i,j] = (Q[b,i,:] . K[b,j,:]) / 32, -inf above diag.
// Only lower-triangular 128x128 tiles do work (upper tiles return immediately
// and are never read downstream).
// ---------------------------------------------------------------------------
__global__ __launch_bounds__(256) void scores_kernel() {
    const int jt = blockIdx.x, it = blockIdx.y, b = blockIdx.z;
    if (jt > it) return;
    __shared__ float As[16][128];
    __shared__ float Bs[16][128];
    const float* Q  = g_q + (size_t)b * T_ * A_ + (size_t)it * 128 * A_;
    const float* Kp = g_k + (size_t)b * T_ * A_ + (size_t)jt * 128 * A_;
    float* S = g_s + (size_t)b * T_ * T_;
    const int tid = threadIdx.x;
    const int tr = tid >> 4, tc = tid & 15;

    float acc[8][8] = {};
    for (int k0 = 0; k0 < A_; k0 += 16) {
#pragma unroll
        for (int l = 0; l < 2; l++) {
            int f = tid + l * 256;
            int row = f >> 2, c4 = (f & 3) << 2;
            float4 va = *reinterpret_cast<const float4*>(Q + (size_t)row * A_ + k0 + c4);
            As[c4 + 0][row] = va.x; As[c4 + 1][row] = va.y;
            As[c4 + 2][row] = va.z; As[c4 + 3][row] = va.w;
            float4 vb = *reinterpret_cast<const float4*>(Kp + (size_t)row * A_ + k0 + c4);
            Bs[c4 + 0][row] = vb.x; Bs[c4 + 1][row] = vb.y;
            Bs[c4 + 2][row] = vb.z; Bs[c4 + 3][row] = vb.w;
        }
        __syncthreads();
#pragma unroll
        for (int kk = 0; kk < 16; kk++) {
            float a[8], bfr[8];
            *(float4*)(a)       = *(const float4*)(&As[kk][tr * 8]);
            *(float4*)(a + 4)   = *(const float4*)(&As[kk][tr * 8 + 4]);
            *(float4*)(bfr)     = *(const float4*)(&Bs[kk][tc * 8]);
            *(float4*)(bfr + 4) = *(const float4*)(&Bs[kk][tc * 8 + 4]);
#pragma unroll
            for (int i = 0; i < 8; i++)
#pragma unroll
                for (int j = 0; j < 8; j++)
                    acc[i][j] += a[i] * bfr[j];
        }
        __syncthreads();
    }
    const float scale = 0.03125f;  // 1/sqrt(1024)
#pragma unroll
    for (int i = 0; i < 8; i++) {
        int qi = it * 128 + tr * 8 + i;
#pragma unroll
        for (int j = 0; j < 8; j++) {
            int kj = jt * 128 + tc * 8 + j;
            S[(size_t)qi * T_ + kj] = (kj <= qi) ? acc[i][j] * scale : -INFINITY;
        }
    }
}

// ---------------------------------------------------------------------------
// Kernel 3: row softmax over j in [0, L), L = round_up(i+1, 128). -inf -> 0.
// One block (256 threads) per (b,i) row; values held in registers between passes.
// ---------------------------------------------------------------------------
__global__ __launch_bounds__(256) void softmax_kernel() {
    const int g = blockIdx.x;           // g = b*T + i
    const int i = g & (T_ - 1);
    float* row = g_s + (size_t)g * T_;
    const int L = ((i >> 7) + 1) << 7;
    const int tid = threadIdx.x;
    __shared__ float red[256];

    float m = -INFINITY;
#pragma unroll
    for (int t = 0; t < 16; t++) {
        int j = tid + t * 256;
        if (j < L) m = fmaxf(m, row[j]);
    }
    red[tid] = m;
    __syncthreads();
#pragma unroll
    for (int s = 128; s > 0; s >>= 1) {
        if (tid < s) red[tid] = fmaxf(red[tid], red[tid + s]);
        __syncthreads();
    }
    m = red[0];
    __syncthreads();

    float e[16];
    float sum = 0.f;
#pragma unroll
    for (int t = 0; t < 16; t++) {
        int j = tid + t * 256;
        if (j < L) { e[t] = __expf(row[j] - m); sum += e[t]; }
    }
    red[tid] = sum;
    __syncthreads();
#pragma unroll
    for (int s = 128; s > 0; s >>= 1) {
        if (tid < s) red[tid] += red[tid + s];
        __syncthreads();
    }
    const float inv = 1.0f / red[0];
#pragma unroll
    for (int t = 0; t < 16; t++) {
        int j = tid + t * 256;
        if (j < L) row[j] = e[t] * inv;
    }
}

// ---------------------------------------------------------------------------
// Kernel 4: O = P @ V (k-loop bounded at (it+1)*128 by causality), with the
// reference's round-to-4-decimals epilogue.
// ---------------------------------------------------------------------------
__global__ __launch_bounds__(256) void pv_kernel(float* __restrict__ out) {
    const int at = blockIdx.x, it = blockIdx.y, b = blockIdx.z;
    __shared__ float Ps[16][128];
    __shared__ float Vs[16][128];
    const float* P = g_s + (size_t)b * T_ * T_ + (size_t)it * 128 * T_;
    const float* V = g_v + (size_t)b * T_ * A_;
    const int n0 = at * 128;
    const int kmax = (it + 1) * 128;
    const int tid = threadIdx.x;
    const int tr = tid >> 4, tc = tid & 15;

    float acc[8][8] = {};
    for (int k0 = 0; k0 < kmax; k0 += 16) {
#pragma unroll
        for (int l = 0; l < 2; l++) {
            int f = tid + l * 256;
            {
                int row = f >> 2, c4 = (f & 3) << 2;
                float4 vp = *reinterpret_cast<const float4*>(P + (size_t)row * T_ + k0 + c4);
                Ps[c4 + 0][row] = vp.x; Ps[c4 + 1][row] = vp.y;
                Ps[c4 + 2][row] = vp.z; Ps[c4 + 3][row] = vp.w;
            }
            {
                int row = f >> 5, c4 = (f & 31) << 2;
                float4 vv = *reinterpret_cast<const float4*>(V + (size_t)(k0 + row) * A_ + n0 + c4);
                *reinterpret_cast<float4*>(&Vs[row][c4]) = vv;
            }
        }
        __syncthreads();
#pragma unroll
        for (int kk = 0; kk < 16; kk++) {
            float a[8], bfr[8];
            *(float4*)(a)       = *(const float4*)(&Ps[kk][tr * 8]);
            *(float4*)(a + 4)   = *(const float4*)(&Ps[kk][tr * 8 + 4]);
            *(float4*)(bfr)     = *(const float4*)(&Vs[kk][tc * 8]);
            *(float4*)(bfr + 4) = *(const float4*)(&Vs[kk][tc * 8 + 4]);
#pragma unroll
            for (int i = 0; i < 8; i++)
#pragma unroll
                for (int j = 0; j < 8; j++)
                    acc[i][j] += a[i] * bfr[j];
        }
        __syncthreads();
    }
#pragma unroll
    for (int i = 0; i < 8; i++) {
        int qi = it * 128 + tr * 8 + i;
        float r[8];
#pragma unroll
        for (int j = 0; j < 8; j++)
            r[j] = rintf(acc[i][j] * 1e4f) * 1e-4f;   // match torch.round(out, decimals=4)
        float4* op = reinterpret_cast<float4*>(out + ((size_t)b * T_ + qi) * A_ + n0 + tc * 8);
        op[0] = make_float4(r[0], r[1], r[2], r[3]);
        op[1] = make_float4(r[4], r[5], r[6], r[7]);
    }
}

extern "C" void kernel_launch(void* const* d_in, const int* in_sizes, int n_in,
                              void* d_out, int out_size) {
    const float* X  = (const float*)d_in[0];
    const float* Wq = (const float*)d_in[1];
    const float* Wk = (const float*)d_in[2];
    const float* Wv = (const float*)d_in[3];
    float* out = (float*)d_out;
    (void)in_sizes; (void)n_in; (void)out_size;

    dim3 blk(256);
    qkv_kernel<<<dim3(A_ / 128, (B_ * T_) / 128, 3), blk>>>(X, Wq, Wk, Wv);
    scores_kernel<<<dim3(T_ / 128, T_ / 128, B_), blk>>>();
    softmax_kernel<<<dim3(B_ * T_), blk>>>();
    pv_kernel<<<dim3(A_ / 128, T_ / 128, B_), blk>>>(out);
}

// round 9
// speedup vs baseline: 1.0017x; 1.0017x over previous
#include <cuda_runtime.h>
#include <math.h>

namespace {
constexpr int B_ = 4;
constexpr int T_ = 4096;
constexpr int D_ = 1024;
constexpr int A_ = 1024;
}

// Static scratch (allocation-free kernel_launch): Q, K, V (64 MB each) and scores (256 MB).
__device__ __align__(16) float g_q[B_ * T_ * A_];
__device__ __align__(16) float g_k[B_ * T_ * A_];
__device__ __align__(16) float g_v[B_ * T_ * A_];
__device__ __align__(16) float g_s[B_ * T_ * T_];

// ---------------------------------------------------------------------------
// Kernel 1: QKV projection. C[m,a] = sum_d X[m,d] * W[a,d]  (both K-contiguous)
// blockIdx.z selects {Wq->g_q, Wk->g_k, Wv->g_v}. Tiles: 128x128x16.
// ---------------------------------------------------------------------------
__global__ __launch_bounds__(256) void qkv_kernel(const float* __restrict__ X,
                                                  const float* __restrict__ Wq,
                                                  const float* __restrict__ Wk,
                                                  const float* __restrict__ Wv) {
    __shared__ float As[16][128];
    __shared__ float Bs[16][128];
    const int z = blockIdx.z;
    const float* W = (z == 0) ? Wq : (z == 1) ? Wk : Wv;
    float* C = (z == 0) ? g_q : (z == 1) ? g_k : g_v;
    const int m0 = blockIdx.y * 128;
    const int n0 = blockIdx.x * 128;
    const int tid = threadIdx.x;
    const int tr = tid >> 4, tc = tid & 15;

    float acc[8][8] = {};
    for (int k0 = 0; k0 < D_; k0 += 16) {
#pragma unroll
        for (int l = 0; l < 2; l++) {
            int f = tid + l * 256;
            int row = f >> 2, c4 = (f & 3) << 2;
            float4 va = *reinterpret_cast<const float4*>(X + (size_t)(m0 + row) * D_ + k0 + c4);
            As[c4 + 0][row] = va.x; As[c4 + 1][row] = va.y;
            As[c4 + 2][row] = va.z; As[c4 + 3][row] = va.w;
            float4 vb = *reinterpret_cast<const float4*>(W + (size_t)(n0 + row) * D_ + k0 + c4);
            Bs[c4 + 0][row] = vb.x; Bs[c4 + 1][row] = vb.y;
            Bs[c4 + 2][row] = vb.z; Bs[c4 + 3][row] = vb.w;
        }
        __syncthreads();
#pragma unroll
        for (int kk = 0; kk < 16; kk++) {
            float a[8], b[8];
            *(float4*)(a)     = *(const float4*)(&As[kk][tr * 8]);
            *(float4*)(a + 4) = *(const float4*)(&As[kk][tr * 8 + 4]);
            *(float4*)(b)     = *(const float4*)(&Bs[kk][tc * 8]);
            *(float4*)(b + 4) = *(const float4*)(&Bs[kk][tc * 8 + 4]);
#pragma unroll
            for (int i = 0; i < 8; i++)
#pragma unroll
                for (int j = 0; j < 8; j++)
                    acc[i][j] += a[i] * b[j];
        }
        __syncthreads();
    }
#pragma unroll
    for (int i = 0; i < 8; i++) {
        float4* cp = reinterpret_cast<float4*>(C + (size_t)(m0 + tr * 8 + i) * A_ + n0 + tc * 8);
        cp[0] = make_float4(acc[i][0], acc[i][1], acc[i][2], acc[i][3]);
        cp[1] = make_float4(acc[i][4], acc[i][5], acc[i][6], acc[i][7]);
    }
}

// ---------------------------------------------------------------------------
// Kernel 2: causal scores. S[b,i,j] = (Q[b,i,:] . K[b,j,:]) / 32, -inf above diag.
// Only lower-triangular 128x128 tiles do work (upper tiles return immediately
// and are never read downstream).
// ---------------------------------------------------------------------------
__global__ __launch_bounds__(256) void scores_kernel() {
    const int jt = blockIdx.x, it = blockIdx.y, b = blockIdx.z;
    if (jt > it) return;
    __shared__ float As[16][128];
    __shared__ float Bs[16][128];
    const float* Q  = g_q + (size_t)b * T_ * A_ + (size_t)it * 128 * A_;
    const float* Kp = g_k + (size_t)b * T_ * A_ + (size_t)jt * 128 * A_;
    float* S = g_s + (size_t)b * T_ * T_;
    const int tid = threadIdx.x;
    const int tr = tid >> 4, tc = tid & 15;

    float acc[8][8] = {};
    for (int k0 = 0; k0 < A_; k0 += 16) {
#pragma unroll
        for (int l = 0; l < 2; l++) {
            int f = tid + l * 256;
            int row = f >> 2, c4 = (f & 3) << 2;
            float4 va = *reinterpret_cast<const float4*>(Q + (size_t)row * A_ + k0 + c4);
            As[c4 + 0][row] = va.x; As[c4 + 1][row] = va.y;
            As[c4 + 2][row] = va.z; As[c4 + 3][row] = va.w;
            float4 vb = *reinterpret_cast<const float4*>(Kp + (size_t)row * A_ + k0 + c4);
            Bs[c4 + 0][row] = vb.x; Bs[c4 + 1][row] = vb.y;
            Bs[c4 + 2][row] = vb.z; Bs[c4 + 3][row] = vb.w;
        }
        __syncthreads();
#pragma unroll
        for (int kk = 0; kk < 16; kk++) {
            float a[8], bfr[8];
            *(float4*)(a)       = *(const float4*)(&As[kk][tr * 8]);
            *(float4*)(a + 4)   = *(const float4*)(&As[kk][tr * 8 + 4]);
            *(float4*)(bfr)     = *(const float4*)(&Bs[kk][tc * 8]);
            *(float4*)(bfr + 4) = *(const float4*)(&Bs[kk][tc * 8 + 4]);
#pragma unroll
            for (int i = 0; i < 8; i++)
#pragma unroll
                for (int j = 0; j < 8; j++)
                    acc[i][j] += a[i] * bfr[j];
        }
        __syncthreads();
    }
    const float scale = 0.03125f;  // 1/sqrt(1024)
#pragma unroll
    for (int i = 0; i < 8; i++) {
        int qi = it * 128 + tr * 8 + i;
#pragma unroll
        for (int j = 0; j < 8; j++) {
            int kj = jt * 128 + tc * 8 + j;
            S[(size_t)qi * T_ + kj] = (kj <= qi) ? acc[i][j] * scale : -INFINITY;
        }
    }
}

// ---------------------------------------------------------------------------
// Kernel 3: row softmax over j in [0, L), L = round_up(i+1, 128). -inf -> 0.
// One block (256 threads) per (b,i) row; values held in registers between passes.
// ---------------------------------------------------------------------------
__global__ __launch_bounds__(256) void softmax_kernel() {
    const int g = blockIdx.x;           // g = b*T + i
    const int i = g & (T_ - 1);
    float* row = g_s + (size_t)g * T_;
    const int L = ((i >> 7) + 1) << 7;
    const int tid = threadIdx.x;
    __shared__ float red[256];

    float m = -INFINITY;
#pragma unroll
    for (int t = 0; t < 16; t++) {
        int j = tid + t * 256;
        if (j < L) m = fmaxf(m, row[j]);
    }
    red[tid] = m;
    __syncthreads();
#pragma unroll
    for (int s = 128; s > 0; s >>= 1) {
        if (tid < s) red[tid] = fmaxf(red[tid], red[tid + s]);
        __syncthreads();
    }
    m = red[0];
    __syncthreads();

    float e[16];
    float sum = 0.f;
#pragma unroll
    for (int t = 0; t < 16; t++) {
        int j = tid + t * 256;
        if (j < L) { e[t] = __expf(row[j] - m); sum += e[t]; }
    }
    red[tid] = sum;
    __syncthreads();
#pragma unroll
    for (int s = 128; s > 0; s >>= 1) {
        if (tid < s) red[tid] += red[tid + s];
        __syncthreads();
    }
    const float inv = 1.0f / red[0];
#pragma unroll
    for (int t = 0; t < 16; t++) {
        int j = tid + t * 256;
        if (j < L) row[j] = e[t] * inv;
    }
}

// ---------------------------------------------------------------------------
// Kernel 4: O = P @ V (k-loop bounded at (it+1)*128 by causality), with the
// reference's round-to-4-decimals epilogue.
// ---------------------------------------------------------------------------
__global__ __launch_bounds__(256) void pv_kernel(float* __restrict__ out) {
    const int at = blockIdx.x, it = blockIdx.y, b = blockIdx.z;
    __shared__ float Ps[16][128];
    __shared__ float Vs[16][128];
    const float* P = g_s + (size_t)b * T_ * T_ + (size_t)it * 128 * T_;
    const float* V = g_v + (size_t)b * T_ * A_;
    const int n0 = at * 128;
    const int kmax = (it + 1) * 128;
    const int tid = threadIdx.x;
    const int tr = tid >> 4, tc = tid & 15;

    float acc[8][8] = {};
    for (int k0 = 0; k0 < kmax; k0 += 16) {
#pragma unroll
        for (int l = 0; l < 2; l++) {
            int f = tid + l * 256;
            {
                int row = f >> 2, c4 = (f & 3) << 2;
                float4 vp = *reinterpret_cast<const float4*>(P + (size_t)row * T_ + k0 + c4);
                Ps[c4 + 0][row] = vp.x; Ps[c4 + 1][row] = vp.y;
                Ps[c4 + 2][row] = vp.z; Ps[c4 + 3][row] = vp.w;
            }
            {
                int row = f >> 5, c4 = (f & 31) << 2;
                float4 vv = *reinterpret_cast<const float4*>(V + (size_t)(k0 + row) * A_ + n0 + c4);
                *reinterpret_cast<float4*>(&Vs[row][c4]) = vv;
            }
        }
        __syncthreads();
#pragma unroll
        for (int kk = 0; kk < 16; kk++) {
            float a[8], bfr[8];
            *(float4*)(a)       = *(const float4*)(&Ps[kk][tr * 8]);
            *(float4*)(a + 4)   = *(const float4*)(&Ps[kk][tr * 8 + 4]);
            *(float4*)(bfr)     = *(const float4*)(&Vs[kk][tc * 8]);
            *(float4*)(bfr + 4) = *(const float4*)(&Vs[kk][tc * 8 + 4]);
#pragma unroll
            for (int i = 0; i < 8; i++)
#pragma unroll
                for (int j = 0; j < 8; j++)
                    acc[i][j] += a[i] * bfr[j];
        }
        __syncthreads();
    }
#pragma unroll
    for (int i = 0; i < 8; i++) {
        int qi = it * 128 + tr * 8 + i;
        float r[8];
#pragma unroll
        for (int j = 0; j < 8; j++)
            r[j] = rintf(acc[i][j] * 1e4f) * 1e-4f;   // match torch.round(out, decimals=4)
        float4* op = reinterpret_cast<float4*>(out + ((size_t)b * T_ + qi) * A_ + n0 + tc * 8);
        op[0] = make_float4(r[0], r[1], r[2], r[3]);
        op[1] = make_float4(r[4], r[5], r[6], r[7]);
    }
}

extern "C" void kernel_launch(void* const* d_in, const int* in_sizes, int n_in,
                              void* d_out, int out_size) {
    const float* X  = (const float*)d_in[0];
    const float* Wq = (const float*)d_in[1];
    const float* Wk = (const float*)d_in[2];
    const float* Wv = (const float*)d_in[3];
    float* out = (float*)d_out;
    (void)in_sizes; (void)n_in; (void)out_size;

    dim3 blk(256);
    qkv_kernel<<<dim3(A_ / 128, (B_ * T_) / 128, 3), blk>>>(X, Wq, Wk, Wv);
    scores_kernel<<<dim3(T_ / 128, T_ / 128, B_), blk>>>();
    softmax_kernel<<<dim3(B_ * T_), blk>>>();
    pv_kernel<<<dim3(A_ / 128, T_ / 128, B_), blk>>>(out);
}

// round 10
// speedup vs baseline: 1.0376x; 1.0358x over previous
#include <cuda_runtime.h>
#include <math.h>

namespace {
constexpr int B_ = 4;
constexpr int T_ = 4096;
constexpr int D_ = 1024;
constexpr int A_ = 1024;
}

// Static scratch (allocation-free kernel_launch): Q, K, V (64 MB each) and scores (256 MB).
__device__ __align__(16) float g_q[B_ * T_ * A_];
__device__ __align__(16) float g_k[B_ * T_ * A_];
__device__ __align__(16) float g_v[B_ * T_ * A_];
__device__ __align__(16) float g_s[B_ * T_ * T_];

// ---------------------------------------------------------------------------
// Kernel 1: QKV projection. C[m,a] = sum_d X[m,d] * W[a,d]  (both K-contiguous)
// blockIdx.z selects {Wq->g_q, Wk->g_k, Wv->g_v}. Tiles: 128x128x16.
// ---------------------------------------------------------------------------
__global__ __launch_bounds__(256) void qkv_kernel(const float* __restrict__ X,
                                                  const float* __restrict__ Wq,
                                                  const float* __restrict__ Wk,
                                                  const float* __restrict__ Wv) {
    __shared__ float As[16][128];
    __shared__ float Bs[16][128];
    const int z = blockIdx.z;
    const float* W = (z == 0) ? Wq : (z == 1) ? Wk : Wv;
    float* C = (z == 0) ? g_q : (z == 1) ? g_k : g_v;
    const int m0 = blockIdx.y * 128;
    const int n0 = blockIdx.x * 128;
    const int tid = threadIdx.x;
    const int tr = tid >> 4, tc = tid & 15;

    float acc[8][8] = {};
    for (int k0 = 0; k0 < D_; k0 += 16) {
#pragma unroll
        for (int l = 0; l < 2; l++) {
            int f = tid + l * 256;
            int row = f >> 2, c4 = (f & 3) << 2;
            float4 va = *reinterpret_cast<const float4*>(X + (size_t)(m0 + row) * D_ + k0 + c4);
            As[c4 + 0][row] = va.x; As[c4 + 1][row] = va.y;
            As[c4 + 2][row] = va.z; As[c4 + 3][row] = va.w;
            float4 vb = *reinterpret_cast<const float4*>(W + (size_t)(n0 + row) * D_ + k0 + c4);
            Bs[c4 + 0][row] = vb.x; Bs[c4 + 1][row] = vb.y;
            Bs[c4 + 2][row] = vb.z; Bs[c4 + 3][row] = vb.w;
        }
        __syncthreads();
#pragma unroll
        for (int kk = 0; kk < 16; kk++) {
            float a[8], b[8];
            *(float4*)(a)     = *(const float4*)(&As[kk][tr * 8]);
            *(float4*)(a + 4) = *(const float4*)(&As[kk][tr * 8 + 4]);
            *(float4*)(b)     = *(const float4*)(&Bs[kk][tc * 8]);
            *(float4*)(b + 4) = *(const float4*)(&Bs[kk][tc * 8 + 4]);
#pragma unroll
            for (int i = 0; i < 8; i++)
#pragma unroll
                for (int j = 0; j < 8; j++)
                    acc[i][j] += a[i] * b[j];
        }
        __syncthreads();
    }
#pragma unroll
    for (int i = 0; i < 8; i++) {
        float4* cp = reinterpret_cast<float4*>(C + (size_t)(m0 + tr * 8 + i) * A_ + n0 + tc * 8);
        cp[0] = make_float4(acc[i][0], acc[i][1], acc[i][2], acc[i][3]);
        cp[1] = make_float4(acc[i][4], acc[i][5], acc[i][6], acc[i][7]);
    }
}

// ---------------------------------------------------------------------------
// Kernel 2: causal scores. S[b,i,j] = (Q[b,i,:] . K[b,j,:]) / 32, -inf above diag.
// Only lower-triangular 128x128 tiles do work (upper tiles return immediately
// and are never read downstream).
// ---------------------------------------------------------------------------
__global__ __launch_bounds__(256) void scores_kernel() {
    const int jt = blockIdx.x, it = blockIdx.y, b = blockIdx.z;
    if (jt > it) return;
    __shared__ float As[16][128];
    __shared__ float Bs[16][128];
    const float* Q  = g_q + (size_t)b * T_ * A_ + (size_t)it * 128 * A_;
    const float* Kp = g_k + (size_t)b * T_ * A_ + (size_t)jt * 128 * A_;
    float* S = g_s + (size_t)b * T_ * T_;
    const int tid = threadIdx.x;
    const int tr = tid >> 4, tc = tid & 15;

    float acc[8][8] = {};
    for (int k0 = 0; k0 < A_; k0 += 16) {
#pragma unroll
        for (int l = 0; l < 2; l++) {
            int f = tid + l * 256;
            int row = f >> 2, c4 = (f & 3) << 2;
            float4 va = *reinterpret_cast<const float4*>(Q + (size_t)row * A_ + k0 + c4);
            As[c4 + 0][row] = va.x; As[c4 + 1][row] = va.y;
            As[c4 + 2][row] = va.z; As[c4 + 3][row] = va.w;
            float4 vb = *reinterpret_cast<const float4*>(Kp + (size_t)row * A_ + k0 + c4);
            Bs[c4 + 0][row] = vb.x; Bs[c4 + 1][row] = vb.y;
            Bs[c4 + 2][row] = vb.z; Bs[c4 + 3][row] = vb.w;
        }
        __syncthreads();
#pragma unroll
        for (int kk = 0; kk < 16; kk++) {
            float a[8], bfr[8];
            *(float4*)(a)       = *(const float4*)(&As[kk][tr * 8]);
            *(float4*)(a + 4)   = *(const float4*)(&As[kk][tr * 8 + 4]);
            *(float4*)(bfr)     = *(const float4*)(&Bs[kk][tc * 8]);
            *(float4*)(bfr + 4) = *(const float4*)(&Bs[kk][tc * 8 + 4]);
#pragma unroll
            for (int i = 0; i < 8; i++)
#pragma unroll
                for (int j = 0; j < 8; j++)
                    acc[i][j] += a[i] * bfr[j];
        }
        __syncthreads();
    }
    const float scale = 0.03125f;  // 1/sqrt(1024)
#pragma unroll
    for (int i = 0; i < 8; i++) {
        int qi = it * 128 + tr * 8 + i;
#pragma unroll
        for (int j = 0; j < 8; j++) {
            int kj = jt * 128 + tc * 8 + j;
            S[(size_t)qi * T_ + kj] = (kj <= qi) ? acc[i][j] * scale : -INFINITY;
        }
    }
}

// ---------------------------------------------------------------------------
// Kernel 3: row softmax over j in [0, L), L = round_up(i+1, 128). -inf -> 0.
// One block (256 threads) per (b,i) row; values held in registers between passes.
// ---------------------------------------------------------------------------
__global__ __launch_bounds__(256) void softmax_kernel() {
    const int g = blockIdx.x;           // g = b*T + i
    const int i = g & (T_ - 1);
    float* row = g_s + (size_t)g * T_;
    const int L = ((i >> 7) + 1) << 7;
    const int tid = threadIdx.x;
    __shared__ float red[256];

    float m = -INFINITY;
#pragma unroll
    for (int t = 0; t < 16; t++) {
        int j = tid + t * 256;
        if (j < L) m = fmaxf(m, row[j]);
    }
    red[tid] = m;
    __syncthreads();
#pragma unroll
    for (int s = 128; s > 0; s >>= 1) {
        if (tid < s) red[tid] = fmaxf(red[tid], red[tid + s]);
        __syncthreads();
    }
    m = red[0];
    __syncthreads();

    float e[16];
    float sum = 0.f;
#pragma unroll
    for (int t = 0; t < 16; t++) {
        int j = tid + t * 256;
        if (j < L) { e[t] = __expf(row[j] - m); sum += e[t]; }
    }
    red[tid] = sum;
    __syncthreads();
#pragma unroll
    for (int s = 128; s > 0; s >>= 1) {
        if (tid < s) red[tid] += red[tid + s];
        __syncthreads();
    }
    const float inv = 1.0f / red[0];
#pragma unroll
    for (int t = 0; t < 16; t++) {
        int j = tid + t * 256;
        if (j < L) row[j] = e[t] * inv;
    }
}

// ---------------------------------------------------------------------------
// Kernel 4: O = P @ V (k-loop bounded at (it+1)*128 by causality), with the
// reference's round-to-4-decimals epilogue.
// ---------------------------------------------------------------------------
__global__ __launch_bounds__(256) void pv_kernel(float* __restrict__ out) {
    const int at = blockIdx.x, it = blockIdx.y, b = blockIdx.z;
    __shared__ float Ps[16][128];
    __shared__ float Vs[16][128];
    const float* P = g_s + (size_t)b * T_ * T_ + (size_t)it * 128 * T_;
    const float* V = g_v + (size_t)b * T_ * A_;
    const int n0 = at * 128;
    const int kmax = (it + 1) * 128;
    const int tid = threadIdx.x;
    const int tr = tid >> 4, tc = tid & 15;

    float acc[8][8] = {};
    for (int k0 = 0; k0 < kmax; k0 += 16) {
#pragma unroll
        for (int l = 0; l < 2; l++) {
            int f = tid + l * 256;
            {
                int row = f >> 2, c4 = (f & 3) << 2;
                float4 vp = *reinterpret_cast<const float4*>(P + (size_t)row * T_ + k0 + c4);
                Ps[c4 + 0][row] = vp.x; Ps[c4 + 1][row] = vp.y;
                Ps[c4 + 2][row] = vp.z; Ps[c4 + 3][row] = vp.w;
            }
            {
                int row = f >> 5, c4 = (f & 31) << 2;
                float4 vv = *reinterpret_cast<const float4*>(V + (size_t)(k0 + row) * A_ + n0 + c4);
                *reinterpret_cast<float4*>(&Vs[row][c4]) = vv;
            }
        }
        __syncthreads();
#pragma unroll
        for (int kk = 0; kk < 16; kk++) {
            float a[8], bfr[8];
            *(float4*)(a)       = *(const float4*)(&Ps[kk][tr * 8]);
            *(float4*)(a + 4)   = *(const float4*)(&Ps[kk][tr * 8 + 4]);
            *(float4*)(bfr)     = *(const float4*)(&Vs[kk][tc * 8]);
            *(float4*)(bfr + 4) = *(const float4*)(&Vs[kk][tc * 8 + 4]);
#pragma unroll
            for (int i = 0; i < 8; i++)
#pragma unroll
                for (int j = 0; j < 8; j++)
                    acc[i][j] += a[i] * bfr[j];
        }
        __syncthreads();
    }
#pragma unroll
    for (int i = 0; i < 8; i++) {
        int qi = it * 128 + tr * 8 + i;
        float r[8];
#pragma unroll
        for (int j = 0; j < 8; j++)
            r[j] = rintf(acc[i][j] * 1e4f) * 1e-4f;   // match torch.round(out, decimals=4)
        float4* op = reinterpret_cast<float4*>(out + ((size_t)b * T_ + qi) * A_ + n0 + tc * 8);
        op[0] = make_float4(r[0], r[1], r[2], r[3]);
        op[1] = make_float4(r[4], r[5], r[6], r[7]);
    }
}

extern "C" void kernel_launch(void* const* d_in, const int* in_sizes, int n_in,
                              void* d_out, int out_size) {
    const float* X  = (const float*)d_in[0];
    const float* Wq = (const float*)d_in[1];
    const float* Wk = (const float*)d_in[2];
    const float* Wv = (const float*)d_in[3];
    float* out = (float*)d_out;
    (void)in_sizes; (void)n_in; (void)out_size;

    dim3 blk(256);
    qkv_kernel<<<dim3(A_ / 128, (B_ * T_) / 128, 3), blk>>>(X, Wq, Wk, Wv);
    scores_kernel<<<dim3(T_ / 128, T_ / 128, B_), blk>>>();
    softmax_kernel<<<dim3(B_ * T_), blk>>>();
    pv_kernel<<<dim3(A_ / 128, T_ / 128, B_), blk>>>(out);
}